// round 17
// baseline (speedup 1.0000x reference)
#include <cuda_runtime.h>
#include <cuda_fp16.h>
#include <math.h>
#include <cstdint>

// Problem constants (fixed shapes)
#define Bb 2
#define Tt 1024
#define Dd 2048
#define Hh 16
#define DH 128
#define MTOT (Bb*Tt)      // 2048
#define DHALF (Dd/2)      // 1024

// ================= helpers (baseline PTX only — no 'a'-suffix features) =================
__device__ __forceinline__ uint32_t smem_to_u32(const void* p) {
    uint32_t a;
    asm("{ .reg .u64 t; cvta.to.shared.u64 t, %1; cvt.u32.u64 %0, t; }" : "=r"(a) : "l"(p));
    return a;
}
__device__ __forceinline__ void ldsm4(uint32_t* r, uint32_t addr) {
    asm volatile("ldmatrix.sync.aligned.m8n8.x4.shared.b16 {%0,%1,%2,%3}, [%4];"
        : "=r"(r[0]), "=r"(r[1]), "=r"(r[2]), "=r"(r[3]) : "r"(addr));
}
__device__ __forceinline__ void ldsm4t(uint32_t* r, uint32_t addr) {
    asm volatile("ldmatrix.sync.aligned.m8n8.x4.trans.shared.b16 {%0,%1,%2,%3}, [%4];"
        : "=r"(r[0]), "=r"(r[1]), "=r"(r[2]), "=r"(r[3]) : "r"(addr));
}
// f32-accum HMMA (non-volatile: register-only, ptxas may schedule)
__device__ __forceinline__ void mma16816(float* c, const uint32_t* a, uint32_t b0, uint32_t b1) {
    asm("mma.sync.aligned.m16n8k16.row.col.f32.f16.f16.f32 "
        "{%0,%1,%2,%3}, {%4,%5,%6,%7}, {%8,%9}, {%0,%1,%2,%3};"
        : "+f"(c[0]), "+f"(c[1]), "+f"(c[2]), "+f"(c[3])
        : "r"(a[0]), "r"(a[1]), "r"(a[2]), "r"(a[3]), "r"(b0), "r"(b1));
}
// f16-accum HMMA probe: same MAC count, possibly 2x issue rate.
// c[0] = halves (row gid: c0,c1), c[1] = halves (row gid+8: c2,c3)
__device__ __forceinline__ void mma16816h(uint32_t* c, const uint32_t* a, uint32_t b0, uint32_t b1) {
    asm("mma.sync.aligned.m16n8k16.row.col.f16.f16.f16.f16 "
        "{%0,%1}, {%2,%3,%4,%5}, {%6,%7}, {%0,%1};"
        : "+r"(c[0]), "+r"(c[1])
        : "r"(a[0]), "r"(a[1]), "r"(a[2]), "r"(a[3]), "r"(b0), "r"(b1));
}
#define CP_ASYNC16(sa, gp) \
    asm volatile("cp.async.cg.shared.global [%0], [%1], 16;" :: "r"(sa), "l"(gp))
#define CP_COMMIT() asm volatile("cp.async.commit_group;" ::: "memory")
#define CP_WAIT1()  asm volatile("cp.async.wait_group 1;" ::: "memory")
#define CP_WAIT0()  asm volatile("cp.async.wait_group 0;" ::: "memory")

// ---------------- scratch (static device globals; no allocation) ----------------
__device__ float g_l2[MTOT*Dd];
__device__ float g_hdn[MTOT*DHALF];
__device__ float g_lam[MTOT*3];

// fp16 buffers: activations hi/lo, weights hi only
__device__ __half g_xh[MTOT*Dd],   g_xl[MTOT*Dd];
__device__ __half g_wqh[Dd*Dd];
__device__ __half g_wkh[Dd*Dd];
__device__ __half g_wvh[Dd*Dd];
__device__ __half g_woh[Dd*Dd];
__device__ __half g_rw1h[DHALF*Dd];
__device__ __half g_qh[MTOT*Dd],   g_ql[MTOT*Dd];
__device__ __half g_fh[MTOT*Dd],   g_fl[MTOT*Dd];
__device__ __half g_ah[MTOT*Dd],   g_al[MTOT*Dd];
__device__ __half g_khh[MTOT*Dd];   // [b,h,t,dh] fp16
__device__ __half g_vhh[MTOT*Dd];

// ---------------- fp32 -> fp16 hi/lo split helpers ----------------
__device__ __forceinline__ void split2h(float a, float b, __half2* hi, __half2* lo) {
    __half h0 = __float2half(a), h1 = __float2half(b);
    *hi = __halves2half2(h0, h1);
    *lo = __halves2half2(__float2half(a - __half2float(h0)),
                         __float2half(b - __half2float(h1)));
}

// 4 equally-sized weight fp32->fp16 conversions in one launch
struct CvtArgs { const float* s[4]; __half* h[4]; };
__global__ void cvt4_kernel(CvtArgs args, int n4) {
    int i = blockIdx.x * blockDim.x + threadIdx.x;
    if (i >= n4) return;
    int z = blockIdx.y;
    float4 v = ((const float4*)args.s[z])[i];
    ((__half2*)args.h[z])[2*i]   = __floats2half2_rn(v.x, v.y);
    ((__half2*)args.h[z])[2*i+1] = __floats2half2_rn(v.z, v.w);
}
__global__ void cvt_kernel(const float* __restrict__ s, __half* __restrict__ h, int n4) {
    int i = blockIdx.x * blockDim.x + threadIdx.x;
    if (i >= n4) return;
    float4 v = ((const float4*)s)[i];
    ((__half2*)h)[2*i]   = __floats2half2_rn(v.x, v.y);
    ((__half2*)h)[2*i+1] = __floats2half2_rn(v.z, v.w);
}

// ---------------- parallel chunked EMA scan + fused x hi/lo split ----------------
__global__ void __launch_bounds__(256)
ema_kernel(const float* __restrict__ x, float* __restrict__ l2,
           __half* __restrict__ xh, __half* __restrict__ xl) {
    const float P64 = 0.0011790184577738583f;   // 0.9^64
    int tid = threadIdx.x;
    int ci = tid & 15, k = tid >> 4;
    int b = blockIdx.x >> 7;
    int c = ((blockIdx.x & 127) << 4) + ci;
    const float* xp = x + (size_t)b * Tt * Dd + c;
    float* lp = l2 + (size_t)b * Tt * Dd + c;
    __half* xhp = xh + (size_t)b * Tt * Dd + c;
    __half* xlp = xl + (size_t)b * Tt * Dd + c;
    const int t0 = k * 64;

    float s = 0.0f;
#pragma unroll 4
    for (int i = 0; i < 64; i++)
        s = 0.9f * s + 0.1f * xp[(size_t)(t0 + i) * Dd];

    __shared__ float endv[16][17], car[16][17];
    endv[k][ci] = s;
    __syncthreads();
    if (k == 0) {
        float carry = 0.0f;
#pragma unroll
        for (int kk = 0; kk < 16; kk++) {
            car[kk][ci] = carry;
            carry = P64 * carry + endv[kk][ci];
        }
    }
    __syncthreads();

    s = car[k][ci];
#pragma unroll 4
    for (int i = 0; i < 64; i++) {
        float xv = xp[(size_t)(t0 + i) * Dd];
        s = 0.9f * s + 0.1f * xv;
        lp[(size_t)(t0 + i) * Dd] = s;
        __half h = __float2half(xv);
        xhp[(size_t)(t0 + i) * Dd] = h;
        xlp[(size_t)(t0 + i) * Dd] = __float2half(xv - __half2float(h));
    }
}

// ================= HMMA fp16 2-pass GEMM =================
// C[M,N] = A[M,K]*B[N,K]^T, D = (Ah+Al)*Bh, fp32 accum (lo optionally f16 accum).
// CTA 128x128, BK=64, warp grid 4(m)x2(n), warp tile 32x64.
// F16LO: lo pass accumulates in fp16 (probe: may run at 2x HMMA rate).
// MINB: min blocks/SM for launch_bounds (1 when extra regs needed & grid<=148).
#define GBK 64
#define GSTR 144
#define GTILEB (128 * GSTR)           // 18432
#define GSTAGE (3 * GTILEB)           // 55296 (Ah, Al, Bh)
#define GSMEM  (2 * GSTAGE)           // 110592

template <int EPI, int F16LO, int MINB>
__global__ void __launch_bounds__(256, MINB)
gemm_tc(const __half* __restrict__ Ah, const __half* __restrict__ Al,
        const __half* __restrict__ Bh, const __half* __restrict__ Bh2,
        const float* __restrict__ bias, float* __restrict__ C, float* __restrict__ C2,
        __half* __restrict__ Chi, __half* __restrict__ Chi2, __half* __restrict__ Clo,
        int N, int K) {
    extern __shared__ char smem[];
    const uint32_t sbase = smem_to_u32(smem);
    const int tid = threadIdx.x;
    const int wid = tid >> 5, lane = tid & 31;
    const int wm = wid & 3, wn = wid >> 2;       // 4(m) x 2(n)
    const int gid = lane >> 2, tig = lane & 3;
    const int m0 = blockIdx.y * 128, n0 = blockIdx.x * 128;

    const __half* Bsel = (EPI == 5 && blockIdx.z) ? Bh2 : Bh;
    float* Csel = (EPI == 5 && blockIdx.z) ? C2 : C;
    __half* Chisel = (EPI == 5 && blockIdx.z) ? Chi2 : Chi;

    const __half* base[3] = {
        Ah + (size_t)m0 * K, Al + (size_t)m0 * K, Bsel + (size_t)n0 * K };

    float acc[2][8][4];
    uint32_t accl[2][8][2];   // f16-accum lo (eliminated by compiler when F16LO=0)
#pragma unroll
    for (int mi = 0; mi < 2; mi++)
#pragma unroll
        for (int nj = 0; nj < 8; nj++) {
#pragma unroll
            for (int r = 0; r < 4; r++) acc[mi][nj][r] = 0.0f;
            if (F16LO) { accl[mi][nj][0] = 0u; accl[mi][nj][1] = 0u; }
        }

    const int NC = K / GBK;

#define LOAD_CHUNK(cc, ss) do { \
        int _c = (cc), _s = (ss); \
_Pragma("unroll") \
        for (int it = 0; it < 12; it++) { \
            int idx = tid + it * 256; \
            int tile = idx >> 10, row = (idx >> 3) & 127, ch = idx & 7; \
            const __half* gp = base[tile] + (size_t)row * K + _c * GBK + ch * 8; \
            uint32_t sa = sbase + _s * GSTAGE + tile * GTILEB + row * GSTR + ch * 16; \
            CP_ASYNC16(sa, gp); \
        } \
    } while (0)

    LOAD_CHUNK(0, 0); CP_COMMIT();

    const int lrow = lane & 15;
    const int lk8  = (lane >> 4) << 3;

    for (int c = 0; c < NC; c++) {
        if (c + 1 < NC) { LOAD_CHUNK(c + 1, (c + 1) & 1); CP_COMMIT(); CP_WAIT1(); }
        else            { CP_WAIT0(); }
        __syncthreads();
        const uint32_t st = sbase + (c & 1) * GSTAGE;
#pragma unroll
        for (int k16 = 0; k16 < 4; k16++) {
            const int k0 = k16 * 16;
            uint32_t bf[4][4];
#pragma unroll
            for (int p = 0; p < 4; p++) {
                int n = wn * 64 + p * 16 + lrow;
                ldsm4(bf[p], st + 2 * GTILEB + n * GSTR + (k0 + lk8) * 2);
            }
#pragma unroll
            for (int mi = 0; mi < 2; mi++) {
                int r = wm * 32 + mi * 16 + lrow;
                uint32_t aa = st + r * GSTR + (k0 + lk8) * 2;
                uint32_t ahf[4], alf[4];
                ldsm4(ahf, aa);
                ldsm4(alf, aa + GTILEB);
                // hi pass (f32 accum) over all 8 accumulators
#pragma unroll
                for (int nj = 0; nj < 8; nj++) {
                    const int p = nj >> 1, q = nj & 1;
                    mma16816(acc[mi][nj], ahf, bf[p][q], bf[p][q + 2]);
                }
                // lo pass: f16 accum (probe) or f32 accum
                if (F16LO) {
#pragma unroll
                    for (int nj = 0; nj < 8; nj++) {
                        const int p = nj >> 1, q = nj & 1;
                        mma16816h(accl[mi][nj], alf, bf[p][q], bf[p][q + 2]);
                    }
                } else {
#pragma unroll
                    for (int nj = 0; nj < 8; nj++) {
                        const int p = nj >> 1, q = nj & 1;
                        mma16816(acc[mi][nj], alf, bf[p][q], bf[p][q + 2]);
                    }
                }
            }
        }
        __syncthreads();
    }
#undef LOAD_CHUNK

    // -------- epilogue --------
#pragma unroll
    for (int mi = 0; mi < 2; mi++) {
#pragma unroll
        for (int nj = 0; nj < 8; nj++) {
            const int colw = wn * 64 + nj * 8 + tig * 2;
#pragma unroll
            for (int half = 0; half < 2; half++) {
                const int m = m0 + wm * 32 + mi * 16 + gid + half * 8;
                float v0 = acc[mi][nj][half * 2 + 0];
                float v1 = acc[mi][nj][half * 2 + 1];
                if (F16LO) {
                    float2 lo = __half22float2(
                        *reinterpret_cast<const __half2*>(&accl[mi][nj][half]));
                    v0 += lo.x; v1 += lo.y;
                }
                if (EPI == 1) {
                    v0 += bias[n0 + colw];
                    v1 += bias[n0 + colw + 1];
                    v0 = v0 / (1.0f + __expf(-v0));
                    v1 = v1 / (1.0f + __expf(-v1));
                }
                if (EPI == 5) {
                    const int bb = m >> 10, t = m & 1023, h = n0 >> 7;
                    size_t off = ((size_t)(bb * Hh + h) * Tt + t) * DH + colw;
                    *(float2*)(Csel + off) = make_float2(v0, v1);
                    *(__half2*)(Chisel + off) = __floats2half2_rn(v0, v1);
                } else if (EPI == 3) {
                    size_t off = (size_t)m * N + n0 + colw;
                    split2h(v0, v1, (__half2*)(Chi + off), (__half2*)(Clo + off));
                } else {
                    float* cp = Csel + (size_t)m * N + n0 + colw;
                    *(float2*)cp = make_float2(v0, v1);
                }
            }
        }
    }
}

// ---------------- router head: one warp per row ----------------
__global__ void __launch_bounds__(256)
router_kernel(const float* __restrict__ hdn, const float* __restrict__ rw2,
              const float* __restrict__ rb2, float* __restrict__ lamA,
              float* __restrict__ lamB) {
    int tid = threadIdx.x;
    int wid = tid >> 5, lane = tid & 31;
    int m = blockIdx.x * 8 + wid;
    const float* hp = hdn + (size_t)m * DHALF;
    float p0 = 0.f, p1 = 0.f, p2 = 0.f;
#pragma unroll 4
    for (int k = lane; k < DHALF; k += 32) {
        float hv = hp[k];
        p0 = fmaf(hv, rw2[k], p0);
        p1 = fmaf(hv, rw2[DHALF + k], p1);
        p2 = fmaf(hv, rw2[2 * DHALF + k], p2);
    }
#pragma unroll
    for (int off = 16; off; off >>= 1) {
        p0 += __shfl_xor_sync(0xffffffffu, p0, off);
        p1 += __shfl_xor_sync(0xffffffffu, p1, off);
        p2 += __shfl_xor_sync(0xffffffffu, p2, off);
    }
    if (lane == 0) {
        float l0 = p0 + rb2[0], l1 = p1 + rb2[1], l2 = p2 + rb2[2];
        float mx = fmaxf(l0, fmaxf(l1, l2));
        float e0 = __expf(l0 - mx), e1 = __expf(l1 - mx), e2 = __expf(l2 - mx);
        float inv = 1.0f / (e0 + e1 + e2);
        float v0 = e0 * inv, v1 = e1 * inv, v2 = e2 * inv;
        lamA[m * 3 + 0] = v0; lamA[m * 3 + 1] = v1; lamA[m * 3 + 2] = v2;
        lamB[m * 3 + 0] = v0; lamB[m * 3 + 1] = v1; lamB[m * 3 + 2] = v2;
    }
}

// ---------------- fused = lam0*x + lam1*l2 + lam2*l3 -> fp16 hi/lo ----------------
__global__ void fuse_kernel(const float* __restrict__ x, const float* __restrict__ l2,
                            const float* __restrict__ l3, const float* __restrict__ lam,
                            __half* __restrict__ fh, __half* __restrict__ fl) {
    int idx = blockIdx.x * blockDim.x + threadIdx.x;
    if (idx >= Bb * Tt * Dd / 4) return;
    int m = idx / (Dd / 4);
    int c = (idx - m * (Dd / 4)) * 4;
    int b = m >> 10;
    const float* lp = lam + (size_t)m * 3;
    float a0 = lp[0], a1 = lp[1], a2 = lp[2];
    float4 xv = *(const float4*)(x + (size_t)m * Dd + c);
    float4 l2v = *(const float4*)(l2 + (size_t)m * Dd + c);
    float4 l3v = *(const float4*)(l3 + (size_t)b * Dd + c);
    float r0 = a0 * xv.x + a1 * l2v.x + a2 * l3v.x;
    float r1 = a0 * xv.y + a1 * l2v.y + a2 * l3v.y;
    float r2 = a0 * xv.z + a1 * l2v.z + a2 * l3v.z;
    float r3 = a0 * xv.w + a1 * l2v.w + a2 * l3v.w;
    size_t off = (size_t)m * Dd + c;
    split2h(r0, r1, (__half2*)(fh + off),     (__half2*)(fl + off));
    split2h(r2, r3, (__half2*)(fh + off) + 1, (__half2*)(fl + off) + 1);
}

// ================= HMMA flash attention (causal), fp16 2-pass =================
// CTA: 128 q-rows, 8 warps, j-blocks of 64. S = Qh*Kh (f32acc) + Ql*Kh (f16acc probe).
// O = (Ph+Pl)*Vh (f32 acc).
#define KVSTR 136
#define KVPLANE (64 * KVSTR * 2)          // 17408
#define KVSTAGE (2 * KVPLANE)             // 34816 (Kh, Vh)
#define PSTR 72
#define PPLANE (128 * PSTR * 2)           // 18432
#define POFF (2 * KVSTAGE)                // 69632
#define ATTN_SMEM (2 * KVSTAGE + 2 * PPLANE)  // 106496

__global__ void __launch_bounds__(256, 1)
attn_tc(const __half* __restrict__ qh, const __half* __restrict__ ql,
        const __half* __restrict__ khh, const __half* __restrict__ vhh,
        __half* __restrict__ ah, __half* __restrict__ al) {
    extern __shared__ char sm[];
    const uint32_t sbase = smem_to_u32(sm);
    const int tid = threadIdx.x;
    const int wid = tid >> 5, lane = tid & 31;
    const int gid = lane >> 2, tig = lane & 3;
    const int qb = 7 - blockIdx.x;            // heavy blocks first
    const int bh = blockIdx.y;
    const int b = bh >> 4, h = bh & 15;
    const int q0 = qb * 128;
    const float scale = 0.08838834764831845f;

    // ---- load Q hi/lo (128x128 fp16 each) into the 2 KV-stage areas
    {
        const __half* qhp = qh + (size_t)(b * Tt + q0) * Dd + h * DH;
        const __half* qlp = ql + (size_t)(b * Tt + q0) * Dd + h * DH;
#pragma unroll
        for (int it = 0; it < 16; it++) {
            int idx = tid + it * 256;
            int plane = idx >> 11;
            int row = (idx >> 4) & 127, ch = idx & 15;
            const __half* gp = (plane ? qlp : qhp) + (size_t)row * Dd + ch * 8;
            uint32_t sa = sbase + plane * KVSTAGE + row * (KVSTR * 2) + ch * 16;
            CP_ASYNC16(sa, gp);
        }
        CP_COMMIT(); CP_WAIT0();
        __syncthreads();
    }
    uint32_t qfh[8][4], qfl[8][4];
    {
        const int m0 = wid * 16;
#pragma unroll
        for (int k16 = 0; k16 < 8; k16++) {
            uint32_t addr = sbase + (m0 + (lane & 15)) * (KVSTR * 2)
                          + (k16 * 16 + ((lane >> 4) << 3)) * 2;
            ldsm4(qfh[k16], addr);
            ldsm4(qfl[k16], addr + KVSTAGE);
        }
    }
    __syncthreads();

    float o[16][4];
#pragma unroll
    for (int nj = 0; nj < 16; nj++)
#pragma unroll
        for (int r = 0; r < 4; r++) o[nj][r] = 0.0f;
    float mi0 = -1e30f, mi1 = -1e30f, li0 = 0.0f, li1 = 0.0f;

    const __half* kb = khh + (size_t)(b * Hh + h) * Tt * DH;
    const __half* vb = vhh + (size_t)(b * Hh + h) * Tt * DH;
    const int njb = 2 * qb + 2;

#define LOAD_KV(jjb, ss) do { \
        int _j0 = (jjb) * 64, _s = (ss); \
_Pragma("unroll") \
        for (int it = 0; it < 8; it++) { \
            int idx = tid + it * 256; \
            int plane = idx >> 10; \
            int row = (idx >> 4) & 63, ch = idx & 15; \
            const __half* gp = (plane ? vb : kb) + (size_t)(_j0 + row) * DH + ch * 8; \
            uint32_t sa = sbase + _s * KVSTAGE + plane * KVPLANE + row * (KVSTR * 2) + ch * 16; \
            CP_ASYNC16(sa, gp); \
        } \
    } while (0)

    LOAD_KV(0, 0); CP_COMMIT();

    for (int jb = 0; jb < njb; jb++) {
        CP_WAIT0();
        __syncthreads();
        if (jb + 1 < njb) { LOAD_KV(jb + 1, (jb + 1) & 1); CP_COMMIT(); }
        const uint32_t st = sbase + (jb & 1) * KVSTAGE;

        // ---- S: hi pass f32 accum, lo pass f16 accum (probe)
        float sacc[8][4];
        uint32_t saccl[8][2];
#pragma unroll
        for (int nj = 0; nj < 8; nj++) {
#pragma unroll
            for (int r = 0; r < 4; r++) sacc[nj][r] = 0.0f;
            saccl[nj][0] = 0u; saccl[nj][1] = 0u;
        }

#pragma unroll
        for (int k16 = 0; k16 < 8; k16++) {
            const int k0 = k16 * 16;
#pragma unroll
            for (int pp = 0; pp < 2; pp++) {
                uint32_t kf[2][4];
#pragma unroll
                for (int pi = 0; pi < 2; pi++) {
                    int n = (pp * 2 + pi) * 16 + (lane & 15);
                    ldsm4(kf[pi], st + n * (KVSTR * 2) + (k0 + ((lane >> 4) << 3)) * 2);
                }
#pragma unroll
                for (int pi = 0; pi < 2; pi++)
#pragma unroll
                    for (int q = 0; q < 2; q++) {
                        int nj = (pp * 2 + pi) * 2 + q;
                        mma16816(sacc[nj], qfh[k16], kf[pi][q], kf[pi][q + 2]);
                    }
#pragma unroll
                for (int pi = 0; pi < 2; pi++)
#pragma unroll
                    for (int q = 0; q < 2; q++) {
                        int nj = (pp * 2 + pi) * 2 + q;
                        mma16816h(saccl[nj], qfl[k16], kf[pi][q], kf[pi][q + 2]);
                    }
            }
        }
        // fold f16 lo accum into f32 S
#pragma unroll
        for (int nj = 0; nj < 8; nj++) {
            float2 a = __half22float2(*reinterpret_cast<const __half2*>(&saccl[nj][0]));
            float2 bq = __half22float2(*reinterpret_cast<const __half2*>(&saccl[nj][1]));
            sacc[nj][0] += a.x;  sacc[nj][1] += a.y;
            sacc[nj][2] += bq.x; sacc[nj][3] += bq.y;
        }

        // scale + causal mask
#pragma unroll
        for (int nj = 0; nj < 8; nj++)
#pragma unroll
            for (int e = 0; e < 4; e++) sacc[nj][e] *= scale;
        if (jb >= 2 * qb) {
            const int rbase = q0 + wid * 16 + gid;
#pragma unroll
            for (int nj = 0; nj < 8; nj++)
#pragma unroll
                for (int e = 0; e < 4; e++) {
                    int col = jb * 64 + nj * 8 + tig * 2 + (e & 1);
                    int row = rbase + ((e >> 1) << 3);
                    if (col > row) sacc[nj][e] = -1e30f;
                }
        }

        // ---- online softmax
        float mx0 = -1e30f, mx1 = -1e30f;
#pragma unroll
        for (int nj = 0; nj < 8; nj++) {
            mx0 = fmaxf(mx0, fmaxf(sacc[nj][0], sacc[nj][1]));
            mx1 = fmaxf(mx1, fmaxf(sacc[nj][2], sacc[nj][3]));
        }
        mx0 = fmaxf(mx0, __shfl_xor_sync(0xffffffffu, mx0, 1));
        mx0 = fmaxf(mx0, __shfl_xor_sync(0xffffffffu, mx0, 2));
        mx1 = fmaxf(mx1, __shfl_xor_sync(0xffffffffu, mx1, 1));
        mx1 = fmaxf(mx1, __shfl_xor_sync(0xffffffffu, mx1, 2));
        float mn0 = fmaxf(mi0, mx0), mn1 = fmaxf(mi1, mx1);
        float corr0 = __expf(mi0 - mn0), corr1 = __expf(mi1 - mn1);
        float rs0 = 0.0f, rs1 = 0.0f;
#pragma unroll
        for (int nj = 0; nj < 8; nj++) {
            sacc[nj][0] = __expf(sacc[nj][0] - mn0); rs0 += sacc[nj][0];
            sacc[nj][1] = __expf(sacc[nj][1] - mn0); rs0 += sacc[nj][1];
            sacc[nj][2] = __expf(sacc[nj][2] - mn1); rs1 += sacc[nj][2];
            sacc[nj][3] = __expf(sacc[nj][3] - mn1); rs1 += sacc[nj][3];
        }
        rs0 += __shfl_xor_sync(0xffffffffu, rs0, 1);
        rs0 += __shfl_xor_sync(0xffffffffu, rs0, 2);
        rs1 += __shfl_xor_sync(0xffffffffu, rs1, 1);
        rs1 += __shfl_xor_sync(0xffffffffu, rs1, 2);
        li0 = li0 * corr0 + rs0; mi0 = mn0;
        li1 = li1 * corr1 + rs1; mi1 = mn1;
#pragma unroll
        for (int nj = 0; nj < 16; nj++) {
            o[nj][0] *= corr0; o[nj][1] *= corr0;
            o[nj][2] *= corr1; o[nj][3] *= corr1;
        }

        // ---- store P hi/lo to smem
        {
            const int pr0 = wid * 16 + gid;
#pragma unroll
            for (int nj = 0; nj < 8; nj++) {
                int col = nj * 8 + tig * 2;
                char* pp0 = sm + POFF + (pr0 * PSTR + col) * 2;
                char* pp1 = sm + POFF + ((pr0 + 8) * PSTR + col) * 2;
                split2h(sacc[nj][0], sacc[nj][1], (__half2*)pp0,
                        (__half2*)(pp0 + PPLANE));
                split2h(sacc[nj][2], sacc[nj][3], (__half2*)pp1,
                        (__half2*)(pp1 + PPLANE));
            }
        }
        __syncthreads();

        // ---- O += (Ph+Pl) Vh; V B-frags via ldmatrix.trans, pair-batched
#pragma unroll
        for (int k16 = 0; k16 < 4; k16++) {
            const int k0j = k16 * 16;
            uint32_t pfh[4], pfl[4];
            uint32_t aaddr = sbase + POFF
                + ((wid * 16 + (lane & 15)) * PSTR + k0j + ((lane >> 4) << 3)) * 2;
            ldsm4(pfh, aaddr);
            ldsm4(pfl, aaddr + PPLANE);
            const int mrow = k0j + (lane & 7) + ((lane >> 4) << 3);
            const int nc8 = ((lane >> 3) & 1) * 8;
#pragma unroll
            for (int pp = 0; pp < 4; pp++) {
                uint32_t vf[2][4];
#pragma unroll
                for (int pi = 0; pi < 2; pi++) {
                    int p = pp * 2 + pi;
                    ldsm4t(vf[pi], st + KVPLANE + mrow * (KVSTR * 2) + (p * 16 + nc8) * 2);
                }
#pragma unroll
                for (int pi = 0; pi < 2; pi++)
#pragma unroll
                    for (int q = 0; q < 2; q++) {
                        int nj = (pp * 2 + pi) * 2 + q;
                        mma16816(o[nj], pfh, vf[pi][q], vf[pi][q + 2]);
                    }
#pragma unroll
                for (int pi = 0; pi < 2; pi++)
#pragma unroll
                    for (int q = 0; q < 2; q++) {
                        int nj = (pp * 2 + pi) * 2 + q;
                        mma16816(o[nj], pfl, vf[pi][q], vf[pi][q + 2]);
                    }
            }
        }
    }
#undef LOAD_KV

    // ---- epilogue: normalize + fp16 hi/lo split to [b,t,d]
    const float inv0 = 1.0f / li0, inv1 = 1.0f / li1;
    const size_t row0 = (size_t)(b * Tt + q0 + wid * 16 + gid) * Dd + h * DH;
    const size_t row1 = row0 + 8 * Dd;
#pragma unroll
    for (int nj = 0; nj < 16; nj++) {
        int col = nj * 8 + tig * 2;
        split2h(o[nj][0] * inv0, o[nj][1] * inv0,
                (__half2*)(ah + row0 + col), (__half2*)(al + row0 + col));
        split2h(o[nj][2] * inv1, o[nj][3] * inv1,
                (__half2*)(ah + row1 + col), (__half2*)(al + row1 + col));
    }
}

// ---------------- launcher ----------------
extern "C" void kernel_launch(void* const* d_in, const int* in_sizes, int n_in,
                              void* d_out, int out_size) {
    (void)in_sizes; (void)n_in; (void)out_size;
    const float* x   = (const float*)d_in[0];
    const float* l3  = (const float*)d_in[1];
    const float* wq  = (const float*)d_in[2];
    const float* wk  = (const float*)d_in[3];
    const float* wv  = (const float*)d_in[4];
    const float* wo  = (const float*)d_in[5];
    const float* rw1 = (const float*)d_in[6];
    const float* rb1 = (const float*)d_in[7];
    const float* rw2 = (const float*)d_in[8];
    const float* rb2 = (const float*)d_in[9];

    float* out = (float*)d_out;
    float* kh  = out + (size_t)Bb * Tt * Dd;
    float* vh  = kh + (size_t)Bb * Tt * Dd;
    float* lam = vh + (size_t)Bb * Tt * Dd;

    float *pl2, *phdn, *plam;
    cudaGetSymbolAddress((void**)&pl2, g_l2);
    cudaGetSymbolAddress((void**)&phdn, g_hdn);
    cudaGetSymbolAddress((void**)&plam, g_lam);

    __half *xh,*xl,*wqh,*wkh,*wvh,*woh,*rw1h;
    __half *qh,*ql,*fh,*fl,*ah,*al,*khh,*vhh;
    cudaGetSymbolAddress((void**)&xh, g_xh);   cudaGetSymbolAddress((void**)&xl, g_xl);
    cudaGetSymbolAddress((void**)&wqh, g_wqh);
    cudaGetSymbolAddress((void**)&wkh, g_wkh);
    cudaGetSymbolAddress((void**)&wvh, g_wvh);
    cudaGetSymbolAddress((void**)&woh, g_woh);
    cudaGetSymbolAddress((void**)&rw1h, g_rw1h);
    cudaGetSymbolAddress((void**)&qh, g_qh);   cudaGetSymbolAddress((void**)&ql, g_ql);
    cudaGetSymbolAddress((void**)&fh, g_fh);   cudaGetSymbolAddress((void**)&fl, g_fl);
    cudaGetSymbolAddress((void**)&ah, g_ah);   cudaGetSymbolAddress((void**)&al, g_al);
    cudaGetSymbolAddress((void**)&khh, g_khh);
    cudaGetSymbolAddress((void**)&vhh, g_vhh);

    cudaFuncSetAttribute(attn_tc, cudaFuncAttributeMaxDynamicSharedMemorySize, ATTN_SMEM);
    cudaFuncSetAttribute((gemm_tc<0,0,2>), cudaFuncAttributeMaxDynamicSharedMemorySize, GSMEM);
    cudaFuncSetAttribute((gemm_tc<1,1,1>), cudaFuncAttributeMaxDynamicSharedMemorySize, GSMEM);
    cudaFuncSetAttribute((gemm_tc<3,0,2>), cudaFuncAttributeMaxDynamicSharedMemorySize, GSMEM);
    cudaFuncSetAttribute((gemm_tc<5,0,2>), cudaFuncAttributeMaxDynamicSharedMemorySize, GSMEM);

    const int NBIG4 = (MTOT * Dd) / 4;
    // 1. EMA scan + fused x hi/lo split
    ema_kernel<<<256, 256>>>(x, pl2, xh, xl);
    // 2. weight fp16 conversions
    CvtArgs ca;
    ca.s[0] = wq;  ca.h[0] = wqh;
    ca.s[1] = wk;  ca.h[1] = wkh;
    ca.s[2] = wv;  ca.h[2] = wvh;
    ca.s[3] = wo;  ca.h[3] = woh;
    cvt4_kernel<<<dim3((NBIG4 + 255) / 256, 4), 256>>>(ca, NBIG4);
    cvt_kernel<<<(NBIG4 / 2 + 255) / 256, 256>>>(rw1, rw1h, NBIG4 / 2);
    // 3. q hi/lo = x @ wq^T
    gemm_tc<3,0,2><<<dim3(16, 16), 256, GSMEM>>>(xh, xl, wqh, nullptr, nullptr,
                                                 nullptr, nullptr, qh, nullptr, ql, Dd, Dd);
    // 4. hdn = silu(q @ rw1^T + rb1)  — f16-accum lo-pass probe (grid 128 <= 148 SMs)
    gemm_tc<1,1,1><<<dim3(8, 16), 256, GSMEM>>>(qh, ql, rw1h, nullptr, rb1,
                                                phdn, nullptr, nullptr, nullptr, nullptr, DHALF, Dd);
    // 5. lam = softmax(hdn @ rw2^T + rb2) — warp-per-row
    router_kernel<<<MTOT / 8, 256>>>(phdn, rw2, rb2, plam, lam);
    // 6. fused mix -> fp16 hi/lo
    fuse_kernel<<<(Bb * Tt * Dd / 4 + 255) / 256, 256>>>(x, pl2, l3, plam, fh, fl);
    // 7. kh/vh = heads(fused @ w^T) — ONE fused launch, z selects wk/wv
    gemm_tc<5,0,2><<<dim3(16, 16, 2), 256, GSMEM>>>(fh, fl, wkh, wvh, nullptr,
                                                    kh, vh, khh, vhh, nullptr, Dd, Dd);
    // 8. HMMA causal flash attention (S-lo f16-accum probe) -> fp16 hi/lo
    attn_tc<<<dim3(8, 32), 256, ATTN_SMEM>>>(qh, ql, khh, vhh, ah, al);
    // 9. out = attn @ wo^T
    gemm_tc<0,0,2><<<dim3(16, 16), 256, GSMEM>>>(ah, al, woh, nullptr, nullptr,
                                                 out, nullptr, nullptr, nullptr, nullptr, Dd, Dd);
}